// round 2
// baseline (speedup 1.0000x reference)
#include <cuda_runtime.h>
#include <math.h>

#define S_SAMPLES 10
#define IN_DIM    512
#define HID_DIM   1024
#define OUT_DIM   512
#define BATCH     1024
#define NPARAMS   (HID_DIM*IN_DIM + OUT_DIM*HID_DIM)   // 1,048,576
#define N1        (HID_DIM*IN_DIM)                      // 524,288

// Scratch (device globals — no allocation allowed in kernel_launch)
static __device__ float g_hm[S_SAMPLES * 10];                 // hidden after 2 elu layers
static __device__ float g_theta[(size_t)S_SAMPLES * NPARAMS]; // 41.9 MB
static __device__ float g_a[(size_t)S_SAMPLES * BATCH * HID_DIM]; // 41.9 MB

__device__ __forceinline__ float elu1(float v) {
    return v > 0.0f ? v : expm1f(v);
}

// ---------------------------------------------------------------------------
// Kernel 1: tiny hypernet trunk. h1 = elu(z @ Wa^T), hm = elu(h1 @ Wb^T)
// z: [10,8], Wa: [10,8], Wb: [10,10]
// ---------------------------------------------------------------------------
__global__ void hyper_trunk_kernel(const float* __restrict__ z,
                                   const float* __restrict__ Wa,
                                   const float* __restrict__ Wb) {
    __shared__ float h1[S_SAMPLES * 10];
    int tid = threadIdx.x;
    if (tid < S_SAMPLES * 10) {
        int s = tid / 10, w = tid % 10;
        float acc = 0.0f;
        #pragma unroll
        for (int c = 0; c < 8; c++) acc += z[s*8 + c] * Wa[w*8 + c];
        h1[tid] = elu1(acc);
    }
    __syncthreads();
    if (tid < S_SAMPLES * 10) {
        int s = tid / 10, v = tid % 10;
        float acc = 0.0f;
        #pragma unroll
        for (int w = 0; w < 10; w++) acc += h1[s*10 + w] * Wb[v*10 + w];
        g_hm[s*10 + v] = elu1(acc);
    }
}

// ---------------------------------------------------------------------------
// Kernel 2: theta[s][p] = sum_v hm[s][v] * Wc[p][v]
// Wc: [NPARAMS, 10] row-major. One thread per p; coalesced 40B reads of Wc,
// coalesced writes per sample.
// ---------------------------------------------------------------------------
__global__ void theta_kernel(const float* __restrict__ Wc) {
    __shared__ float hm_s[S_SAMPLES * 10];
    if (threadIdx.x < S_SAMPLES * 10) hm_s[threadIdx.x] = g_hm[threadIdx.x];
    __syncthreads();

    int p = blockIdx.x * blockDim.x + threadIdx.x;
    if (p >= NPARAMS) return;

    float wc[10];
    #pragma unroll
    for (int v = 0; v < 10; v++) wc[v] = Wc[(size_t)p*10 + v];

    #pragma unroll
    for (int s = 0; s < S_SAMPLES; s++) {
        float acc = 0.0f;
        #pragma unroll
        for (int v = 0; v < 10; v++) acc += hm_s[s*10 + v] * wc[v];
        g_theta[(size_t)s * NPARAMS + p] = acc;
    }
}

// ---------------------------------------------------------------------------
// Kernel 3: NT SGEMM, C[m][n] = sum_k A[m][k] * Bm[n][k], optional elu.
// 128x128 block tile, BK=8, 256 threads, 8x8 per thread. Batched over z = s.
// ---------------------------------------------------------------------------
template<bool ELU>
__global__ __launch_bounds__(256, 2)
void sgemm_nt_kernel(const float* __restrict__ A, size_t strideA,
                     const float* __restrict__ Bm, size_t strideB,
                     float* __restrict__ C, size_t strideC,
                     int N, int K) {
    const int s = blockIdx.z;
    A  += (size_t)s * strideA;
    Bm += (size_t)s * strideB;
    C  += (size_t)s * strideC;

    const int m0 = blockIdx.y * 128;
    const int n0 = blockIdx.x * 128;

    __shared__ float As[8][128];
    __shared__ float Bs[8][128];

    const int tid = threadIdx.x;
    const int lr  = tid >> 1;          // 0..127 tile row for loads
    const int lc  = (tid & 1) * 4;     // 0 or 4 (float4 column within BK=8)
    const int ty  = tid >> 4;          // 0..15
    const int tx  = tid & 15;          // 0..15

    float acc[8][8];
    #pragma unroll
    for (int i = 0; i < 8; i++)
        #pragma unroll
        for (int j = 0; j < 8; j++) acc[i][j] = 0.0f;

    for (int k0 = 0; k0 < K; k0 += 8) {
        float4 av = *(const float4*)(A  + (size_t)(m0 + lr) * K + k0 + lc);
        float4 bv = *(const float4*)(Bm + (size_t)(n0 + lr) * K + k0 + lc);
        As[lc+0][lr] = av.x; As[lc+1][lr] = av.y;
        As[lc+2][lr] = av.z; As[lc+3][lr] = av.w;
        Bs[lc+0][lr] = bv.x; Bs[lc+1][lr] = bv.y;
        Bs[lc+2][lr] = bv.z; Bs[lc+3][lr] = bv.w;
        __syncthreads();

        #pragma unroll
        for (int kk = 0; kk < 8; kk++) {
            float a[8], b[8];
            *(float4*)(a)     = *(const float4*)&As[kk][ty*8];
            *(float4*)(a + 4) = *(const float4*)&As[kk][ty*8 + 4];
            *(float4*)(b)     = *(const float4*)&Bs[kk][tx*8];
            *(float4*)(b + 4) = *(const float4*)&Bs[kk][tx*8 + 4];
            #pragma unroll
            for (int i = 0; i < 8; i++)
                #pragma unroll
                for (int j = 0; j < 8; j++)
                    acc[i][j] = fmaf(a[i], b[j], acc[i][j]);
        }
        __syncthreads();
    }

    #pragma unroll
    for (int i = 0; i < 8; i++) {
        const int row = m0 + ty*8 + i;
        float* crow = C + (size_t)row * N + n0 + tx*8;
        float4 v0, v1;
        if (ELU) {
            v0.x = elu1(acc[i][0]); v0.y = elu1(acc[i][1]);
            v0.z = elu1(acc[i][2]); v0.w = elu1(acc[i][3]);
            v1.x = elu1(acc[i][4]); v1.y = elu1(acc[i][5]);
            v1.z = elu1(acc[i][6]); v1.w = elu1(acc[i][7]);
        } else {
            v0.x = acc[i][0]; v0.y = acc[i][1];
            v0.z = acc[i][2]; v0.w = acc[i][3];
            v1.x = acc[i][4]; v1.y = acc[i][5];
            v1.z = acc[i][6]; v1.w = acc[i][7];
        }
        *(float4*)(crow)     = v0;
        *(float4*)(crow + 4) = v1;
    }
}

// ---------------------------------------------------------------------------
// Launch
// Inputs (metadata order): x [1024,512], z [10,8], Wa [10,8], Wb [10,10],
//                          Wc [1048576,10], samples (int scalar, ignored)
// Output: y [10, 1024, 512] fp32
// ---------------------------------------------------------------------------
extern "C" void kernel_launch(void* const* d_in, const int* in_sizes, int n_in,
                              void* d_out, int out_size) {
    const float* x  = (const float*)d_in[0];
    const float* z  = (const float*)d_in[1];
    const float* Wa = (const float*)d_in[2];
    const float* Wb = (const float*)d_in[3];
    const float* Wc = (const float*)d_in[4];
    float* out = (float*)d_out;

    (void)in_sizes; (void)n_in; (void)out_size;

    float* theta; cudaGetSymbolAddress((void**)&theta, g_theta);
    float* a_buf; cudaGetSymbolAddress((void**)&a_buf, g_a);

    // 1) Tiny trunk
    hyper_trunk_kernel<<<1, 128>>>(z, Wa, Wb);

    // 2) theta = hm @ Wc^T
    theta_kernel<<<(NPARAMS + 255) / 256, 256>>>(Wc);

    // 3) a[s] = elu(x @ W1[s]^T)   (M=1024, N=1024, K=512)
    {
        dim3 grid(HID_DIM / 128, BATCH / 128, S_SAMPLES);
        sgemm_nt_kernel<true><<<grid, 256>>>(
            x, 0,                                   // x shared across samples
            theta, (size_t)NPARAMS,                 // W1[s] = theta[s][:N1], [1024,512]
            a_buf, (size_t)BATCH * HID_DIM,
            HID_DIM, IN_DIM);
    }

    // 4) y[s] = a[s] @ W2[s]^T     (M=1024, N=512, K=1024)
    {
        dim3 grid(OUT_DIM / 128, BATCH / 128, S_SAMPLES);
        sgemm_nt_kernel<false><<<grid, 256>>>(
            a_buf, (size_t)BATCH * HID_DIM,
            theta + N1, (size_t)NPARAMS,            // W2[s], [512,1024]
            out, (size_t)BATCH * OUT_DIM,
            OUT_DIM, HID_DIM);
    }
}

// round 4
// speedup vs baseline: 2.4074x; 2.4074x over previous
#include <cuda_runtime.h>
#include <cuda_bf16.h>
#include <stdint.h>
#include <math.h>

#define S_SAMPLES 10
#define IN_DIM    512
#define HID_DIM   1024
#define OUT_DIM   512
#define BATCH     1024
#define NPARAMS   (HID_DIM*IN_DIM + OUT_DIM*HID_DIM)   // 1,048,576
#define N1        (HID_DIM*IN_DIM)                      // 524,288

// ---------------------------------------------------------------------------
// Scratch (device globals — no allocation allowed)
// ---------------------------------------------------------------------------
static __device__ float g_hm[S_SAMPLES * 10];
static __device__ __nv_bfloat16 g_xh[BATCH * IN_DIM];
static __device__ __nv_bfloat16 g_xl[BATCH * IN_DIM];
static __device__ __nv_bfloat16 g_th[(size_t)S_SAMPLES * NPARAMS];
static __device__ __nv_bfloat16 g_tl[(size_t)S_SAMPLES * NPARAMS];
static __device__ __nv_bfloat16 g_ah[(size_t)S_SAMPLES * BATCH * HID_DIM];
static __device__ __nv_bfloat16 g_al[(size_t)S_SAMPLES * BATCH * HID_DIM];

__device__ __forceinline__ float elu1(float v) { return v > 0.0f ? v : expm1f(v); }

// ---------------------------------------------------------------------------
// PTX helpers (portable: sm_80+ instructions only)
// ---------------------------------------------------------------------------
__device__ __forceinline__ uint32_t smem_u32(const void* p) {
    uint32_t a;
    asm("{ .reg .u64 t; cvta.to.shared.u64 t, %1; cvt.u32.u64 %0, t; }" : "=r"(a) : "l"(p));
    return a;
}
__device__ __forceinline__ void cp_async16(const void* smem_dst, const void* gmem_src) {
    asm volatile("cp.async.cg.shared.global [%0], [%1], 16;"
                 :: "r"(smem_u32(smem_dst)), "l"(gmem_src));
}
__device__ __forceinline__ void cp_commit() {
    asm volatile("cp.async.commit_group;");
}
__device__ __forceinline__ void cp_wait1() {
    asm volatile("cp.async.wait_group 1;");
}
__device__ __forceinline__ void cp_wait0() {
    asm volatile("cp.async.wait_group 0;");
}
__device__ __forceinline__ void ldsm4(uint32_t* r, uint32_t addr) {
    asm volatile("ldmatrix.sync.aligned.m8n8.x4.shared.b16 {%0,%1,%2,%3}, [%4];"
                 : "=r"(r[0]), "=r"(r[1]), "=r"(r[2]), "=r"(r[3]) : "r"(addr));
}
__device__ __forceinline__ void mma16816(float* d, const uint32_t* a, const uint32_t* b) {
    asm volatile("mma.sync.aligned.m16n8k16.row.col.f32.bf16.bf16.f32 "
                 "{%0,%1,%2,%3}, {%4,%5,%6,%7}, {%8,%9}, {%0,%1,%2,%3};"
                 : "+f"(d[0]), "+f"(d[1]), "+f"(d[2]), "+f"(d[3])
                 : "r"(a[0]), "r"(a[1]), "r"(a[2]), "r"(a[3]), "r"(b[0]), "r"(b[1]));
}

// ---------------------------------------------------------------------------
// Kernel 1: tiny hypernet trunk
// ---------------------------------------------------------------------------
__global__ void hyper_trunk_kernel(const float* __restrict__ z,
                                   const float* __restrict__ Wa,
                                   const float* __restrict__ Wb) {
    __shared__ float h1[S_SAMPLES * 10];
    int tid = threadIdx.x;
    if (tid < S_SAMPLES * 10) {
        int s = tid / 10, w = tid % 10;
        float acc = 0.0f;
        #pragma unroll
        for (int c = 0; c < 8; c++) acc += z[s*8 + c] * Wa[w*8 + c];
        h1[tid] = elu1(acc);
    }
    __syncthreads();
    if (tid < S_SAMPLES * 10) {
        int s = tid / 10, v = tid % 10;
        float acc = 0.0f;
        #pragma unroll
        for (int w = 0; w < 10; w++) acc += h1[s*10 + w] * Wb[v*10 + w];
        g_hm[s*10 + v] = elu1(acc);
    }
}

// ---------------------------------------------------------------------------
// Kernel 2: x -> bf16 hi/lo split
// ---------------------------------------------------------------------------
__global__ void xconv_kernel(const float* __restrict__ x) {
    int i4 = blockIdx.x * blockDim.x + threadIdx.x;
    if (i4 * 4 >= BATCH * IN_DIM) return;
    float4 v = reinterpret_cast<const float4*>(x)[i4];
    float f[4] = {v.x, v.y, v.z, v.w};
    __nv_bfloat16 h[4], l[4];
    #pragma unroll
    for (int j = 0; j < 4; j++) {
        h[j] = __float2bfloat16(f[j]);
        l[j] = __float2bfloat16(f[j] - __bfloat162float(h[j]));
    }
    __nv_bfloat162 h01 = __halves2bfloat162(h[0], h[1]);
    __nv_bfloat162 h23 = __halves2bfloat162(h[2], h[3]);
    __nv_bfloat162 l01 = __halves2bfloat162(l[0], l[1]);
    __nv_bfloat162 l23 = __halves2bfloat162(l[2], l[3]);
    reinterpret_cast<uint2*>(g_xh)[i4] = make_uint2(*(uint32_t*)&h01, *(uint32_t*)&h23);
    reinterpret_cast<uint2*>(g_xl)[i4] = make_uint2(*(uint32_t*)&l01, *(uint32_t*)&l23);
}

// ---------------------------------------------------------------------------
// Kernel 3: theta[s][p] = sum_v hm[s][v] * Wc[p][v] -> bf16 hi/lo
// ---------------------------------------------------------------------------
__global__ void theta_kernel(const float* __restrict__ Wc) {
    __shared__ float hm_s[S_SAMPLES * 10];
    if (threadIdx.x < S_SAMPLES * 10) hm_s[threadIdx.x] = g_hm[threadIdx.x];
    __syncthreads();

    int p0 = (blockIdx.x * blockDim.x + threadIdx.x) * 2;
    if (p0 >= NPARAMS) return;

    float wc0[10], wc1[10];
    #pragma unroll
    for (int v = 0; v < 10; v++) {
        wc0[v] = Wc[(size_t)p0 * 10 + v];
        wc1[v] = Wc[(size_t)(p0 + 1) * 10 + v];
    }
    #pragma unroll
    for (int s = 0; s < S_SAMPLES; s++) {
        float a0 = 0.0f, a1 = 0.0f;
        #pragma unroll
        for (int v = 0; v < 10; v++) {
            a0 += hm_s[s*10 + v] * wc0[v];
            a1 += hm_s[s*10 + v] * wc1[v];
        }
        __nv_bfloat16 h0 = __float2bfloat16(a0), h1 = __float2bfloat16(a1);
        __nv_bfloat16 l0 = __float2bfloat16(a0 - __bfloat162float(h0));
        __nv_bfloat16 l1 = __float2bfloat16(a1 - __bfloat162float(h1));
        __nv_bfloat162 hp = __halves2bfloat162(h0, h1);
        __nv_bfloat162 lp = __halves2bfloat162(l0, l1);
        *reinterpret_cast<uint32_t*>(g_th + (size_t)s * NPARAMS + p0) = *(uint32_t*)&hp;
        *reinterpret_cast<uint32_t*>(g_tl + (size_t)s * NPARAMS + p0) = *(uint32_t*)&lp;
    }
}

// ---------------------------------------------------------------------------
// Kernel 4: mma.sync NT GEMM with bf16-split (3 HMMA per product term).
// C[m][n] = sum_k A[m][k]*B[n][k]. 128x128 CTA tile, 8 warps (4Mx2N),
// warp tile 32x64, KC=32, 2-stage cp.async pipeline.
// SMEM rows padded to 40 bf16 (80B) -> ldmatrix conflict-free.
// ---------------------------------------------------------------------------
#define KC      32
#define SMS     40                   // padded row stride (elems)
#define TILE_E  (128 * SMS)          // 5120 elems per tile
#define STAGE_E (4 * TILE_E)         // Ah, Al, Bh, Bl
#define SMEM_BYTES (2 * STAGE_E * 2) // 81920

template<bool LAYER1>
__global__ __launch_bounds__(256, 1)
void mma_gemm_kernel(const __nv_bfloat16* __restrict__ Ah_, const __nv_bfloat16* __restrict__ Al_,
                     unsigned long long sA, int lda,
                     const __nv_bfloat16* __restrict__ Bh_, const __nv_bfloat16* __restrict__ Bl_,
                     unsigned long long sB, int ldb,
                     float* __restrict__ Cf,
                     __nv_bfloat16* __restrict__ Ch, __nv_bfloat16* __restrict__ Cl,
                     unsigned long long sC, int ldc, int K) {
    extern __shared__ __nv_bfloat16 sm[];
    const int tid  = threadIdx.x;
    const int lane = tid & 31, wid = tid >> 5;
    const int warpM = wid & 3, warpN = wid >> 2;
    const int s  = blockIdx.z;
    const int m0 = blockIdx.y * 128;
    const int n0 = blockIdx.x * 128;

    const __nv_bfloat16* Ah = Ah_ + (size_t)s * sA;
    const __nv_bfloat16* Al = Al_ + (size_t)s * sA;
    const __nv_bfloat16* Bh = Bh_ + (size_t)s * sB;
    const __nv_bfloat16* Bl = Bl_ + (size_t)s * sB;

    const int row = tid >> 2;          // 0..63 then +64 on 2nd iter? no: idx>>2
    (void)row;

    float acc[2][8][4];
    #pragma unroll
    for (int i = 0; i < 2; i++)
        #pragma unroll
        for (int j = 0; j < 8; j++)
            #pragma unroll
            for (int q = 0; q < 4; q++) acc[i][j][q] = 0.0f;

    const int NC = K >> 5;

    // prefetch chunk 0
    {
        __nv_bfloat16* st = sm;
        #pragma unroll
        for (int it = 0; it < 2; it++) {
            int idx = it * 256 + tid;
            int r = idx >> 2, v = (idx & 3) * 8;
            cp_async16(&st[0 * TILE_E + r * SMS + v], Ah + (size_t)(m0 + r) * lda + v);
            cp_async16(&st[1 * TILE_E + r * SMS + v], Al + (size_t)(m0 + r) * lda + v);
            cp_async16(&st[2 * TILE_E + r * SMS + v], Bh + (size_t)(n0 + r) * ldb + v);
            cp_async16(&st[3 * TILE_E + r * SMS + v], Bl + (size_t)(n0 + r) * ldb + v);
        }
        cp_commit();
    }

    for (int c = 0; c < NC; c++) {
        if (c + 1 < NC) {
            __nv_bfloat16* st = sm + ((c + 1) & 1) * STAGE_E;
            const int k0 = (c + 1) * KC;
            #pragma unroll
            for (int it = 0; it < 2; it++) {
                int idx = it * 256 + tid;
                int r = idx >> 2, v = (idx & 3) * 8;
                cp_async16(&st[0 * TILE_E + r * SMS + v], Ah + (size_t)(m0 + r) * lda + k0 + v);
                cp_async16(&st[1 * TILE_E + r * SMS + v], Al + (size_t)(m0 + r) * lda + k0 + v);
                cp_async16(&st[2 * TILE_E + r * SMS + v], Bh + (size_t)(n0 + r) * ldb + k0 + v);
                cp_async16(&st[3 * TILE_E + r * SMS + v], Bl + (size_t)(n0 + r) * ldb + k0 + v);
            }
            cp_commit();
            cp_wait1();
        } else {
            cp_wait0();
        }
        __syncthreads();

        const uint32_t base = smem_u32(sm + (c & 1) * STAGE_E);
        #pragma unroll
        for (int ks = 0; ks < 2; ks++) {
            uint32_t afh[2][4], afl[2][4], bfh[8][2], bfl[8][2];
            #pragma unroll
            for (int i = 0; i < 2; i++) {
                uint32_t off = ((warpM * 32 + i * 16 + (lane & 15)) * SMS
                                + ks * 16 + ((lane >> 4) << 3)) * 2;
                ldsm4(afh[i], base + off);
                ldsm4(afl[i], base + TILE_E * 2 + off);
            }
            #pragma unroll
            for (int j4 = 0; j4 < 4; j4++) {
                int rr = (lane & 7) + ((lane >> 4) & 1) * 8;
                int kh = (lane >> 3) & 1;
                uint32_t off = ((warpN * 64 + j4 * 16 + rr) * SMS + ks * 16 + kh * 8) * 2;
                uint32_t t4[4];
                ldsm4(t4, base + 2 * TILE_E * 2 + off);
                bfh[2*j4][0] = t4[0]; bfh[2*j4][1] = t4[1];
                bfh[2*j4+1][0] = t4[2]; bfh[2*j4+1][1] = t4[3];
                ldsm4(t4, base + 3 * TILE_E * 2 + off);
                bfl[2*j4][0] = t4[0]; bfl[2*j4][1] = t4[1];
                bfl[2*j4+1][0] = t4[2]; bfl[2*j4+1][1] = t4[3];
            }
            #pragma unroll
            for (int i = 0; i < 2; i++)
                #pragma unroll
                for (int j = 0; j < 8; j++) {
                    mma16816(acc[i][j], afh[i], bfh[j]);
                    mma16816(acc[i][j], afh[i], bfl[j]);
                    mma16816(acc[i][j], afl[i], bfh[j]);
                }
        }
        __syncthreads();
    }

    // Epilogue. d-reg mapping: d0=(r, c), d1=(r, c+1), d2=(r+8, c), d3=(r+8, c+1)
    // with r = lane>>2, c = (lane&3)*2.
    #pragma unroll
    for (int i = 0; i < 2; i++) {
        int gm = m0 + warpM * 32 + i * 16 + (lane >> 2);
        #pragma unroll
        for (int j = 0; j < 8; j++) {
            int gn = n0 + warpN * 64 + j * 8 + (lane & 3) * 2;
            float* d = acc[i][j];
            if (LAYER1) {
                #pragma unroll
                for (int half = 0; half < 2; half++) {
                    int r = gm + half * 8;
                    float v0 = elu1(d[half * 2 + 0]);
                    float v1 = elu1(d[half * 2 + 1]);
                    __nv_bfloat16 h0 = __float2bfloat16(v0), h1 = __float2bfloat16(v1);
                    __nv_bfloat16 l0 = __float2bfloat16(v0 - __bfloat162float(h0));
                    __nv_bfloat16 l1 = __float2bfloat16(v1 - __bfloat162float(h1));
                    __nv_bfloat162 hp = __halves2bfloat162(h0, h1);
                    __nv_bfloat162 lp = __halves2bfloat162(l0, l1);
                    size_t off = (size_t)s * sC + (size_t)r * ldc + gn;
                    *reinterpret_cast<uint32_t*>(Ch + off) = *(uint32_t*)&hp;
                    *reinterpret_cast<uint32_t*>(Cl + off) = *(uint32_t*)&lp;
                }
            } else {
                size_t off0 = (size_t)s * sC + (size_t)gm * ldc + gn;
                size_t off1 = (size_t)s * sC + (size_t)(gm + 8) * ldc + gn;
                *reinterpret_cast<float2*>(Cf + off0) = make_float2(d[0], d[1]);
                *reinterpret_cast<float2*>(Cf + off1) = make_float2(d[2], d[3]);
            }
        }
    }
}

// ---------------------------------------------------------------------------
// Launch
// Inputs: x [1024,512], z [10,8], Wa [10,8], Wb [10,10], Wc [1048576,10], samples
// Output: y [10, 1024, 512] fp32
// ---------------------------------------------------------------------------
extern "C" void kernel_launch(void* const* d_in, const int* in_sizes, int n_in,
                              void* d_out, int out_size) {
    const float* x  = (const float*)d_in[0];
    const float* z  = (const float*)d_in[1];
    const float* Wa = (const float*)d_in[2];
    const float* Wb = (const float*)d_in[3];
    const float* Wc = (const float*)d_in[4];
    float* out = (float*)d_out;
    (void)in_sizes; (void)n_in; (void)out_size;

    __nv_bfloat16 *xh, *xl, *th, *tl, *ah, *al;
    cudaGetSymbolAddress((void**)&xh, g_xh);
    cudaGetSymbolAddress((void**)&xl, g_xl);
    cudaGetSymbolAddress((void**)&th, g_th);
    cudaGetSymbolAddress((void**)&tl, g_tl);
    cudaGetSymbolAddress((void**)&ah, g_ah);
    cudaGetSymbolAddress((void**)&al, g_al);

    static bool attr_done = false;
    if (!attr_done) {
        cudaFuncSetAttribute(mma_gemm_kernel<true>,
                             cudaFuncAttributeMaxDynamicSharedMemorySize, SMEM_BYTES);
        cudaFuncSetAttribute(mma_gemm_kernel<false>,
                             cudaFuncAttributeMaxDynamicSharedMemorySize, SMEM_BYTES);
        attr_done = true;
    }

    // 1) trunk + x conversion (independent)
    hyper_trunk_kernel<<<1, 128>>>(z, Wa, Wb);
    xconv_kernel<<<(BATCH * IN_DIM / 4 + 255) / 256, 256>>>(x);

    // 2) theta -> bf16 hi/lo
    theta_kernel<<<(NPARAMS / 2 + 255) / 256, 256>>>(Wc);

    // 3) a[s] = elu(x @ W1[s]^T)  M=1024, N=1024, K=512
    {
        dim3 grid(HID_DIM / 128, BATCH / 128, S_SAMPLES);
        mma_gemm_kernel<true><<<grid, 256, SMEM_BYTES>>>(
            xh, xl, 0ull, IN_DIM,
            th, tl, (unsigned long long)NPARAMS, IN_DIM,
            nullptr, ah, al,
            (unsigned long long)(BATCH * HID_DIM), HID_DIM, IN_DIM);
    }

    // 4) y[s] = a[s] @ W2[s]^T    M=1024, N=512, K=1024
    {
        dim3 grid(OUT_DIM / 128, BATCH / 128, S_SAMPLES);
        mma_gemm_kernel<false><<<grid, 256, SMEM_BYTES>>>(
            ah, al, (unsigned long long)(BATCH * HID_DIM), HID_DIM,
            th + N1, tl + N1, (unsigned long long)NPARAMS, HID_DIM,
            out, nullptr, nullptr,
            (unsigned long long)(BATCH * OUT_DIM), OUT_DIM, HID_DIM);
    }
}

// round 6
// speedup vs baseline: 2.9561x; 1.2279x over previous
#include <cuda_runtime.h>
#include <cuda_bf16.h>
#include <stdint.h>
#include <math.h>

#define S_SAMPLES 10
#define IN_DIM    512
#define HID_DIM   1024
#define OUT_DIM   512
#define BATCH     1024
#define NPARAMS   (HID_DIM*IN_DIM + OUT_DIM*HID_DIM)   // 1,048,576
#define N1        (HID_DIM*IN_DIM)                      // 524,288

// ---------------------------------------------------------------------------
// Scratch (device globals — no allocation allowed)
// ---------------------------------------------------------------------------
static __device__ float g_hm[S_SAMPLES * 10];
static __device__ __nv_bfloat16 g_xh[BATCH * IN_DIM];
static __device__ __nv_bfloat16 g_xl[BATCH * IN_DIM];
static __device__ __nv_bfloat16 g_th[(size_t)S_SAMPLES * NPARAMS];
static __device__ __nv_bfloat16 g_tl[(size_t)S_SAMPLES * NPARAMS];
static __device__ __nv_bfloat16 g_ah[(size_t)S_SAMPLES * BATCH * HID_DIM];
static __device__ __nv_bfloat16 g_al[(size_t)S_SAMPLES * BATCH * HID_DIM];

__device__ __forceinline__ float elu1(float v) { return v > 0.0f ? v : expm1f(v); }

// ---------------------------------------------------------------------------
// PTX helpers (portable: sm_80+ instructions only)
// ---------------------------------------------------------------------------
__device__ __forceinline__ uint32_t smem_u32(const void* p) {
    uint32_t a;
    asm("{ .reg .u64 t; cvta.to.shared.u64 t, %1; cvt.u32.u64 %0, t; }" : "=r"(a) : "l"(p));
    return a;
}
__device__ __forceinline__ void cp_async16(const void* smem_dst, const void* gmem_src) {
    asm volatile("cp.async.cg.shared.global [%0], [%1], 16;"
                 :: "r"(smem_u32(smem_dst)), "l"(gmem_src));
}
__device__ __forceinline__ void cp_commit() {
    asm volatile("cp.async.commit_group;");
}
__device__ __forceinline__ void cp_wait1() {
    asm volatile("cp.async.wait_group 1;");
}
__device__ __forceinline__ void cp_wait0() {
    asm volatile("cp.async.wait_group 0;");
}
__device__ __forceinline__ void ldsm4(uint32_t* r, uint32_t addr) {
    asm volatile("ldmatrix.sync.aligned.m8n8.x4.shared.b16 {%0,%1,%2,%3}, [%4];"
                 : "=r"(r[0]), "=r"(r[1]), "=r"(r[2]), "=r"(r[3]) : "r"(addr));
}
__device__ __forceinline__ void mma16816(float* d, const uint32_t* a, const uint32_t* b) {
    asm volatile("mma.sync.aligned.m16n8k16.row.col.f32.bf16.bf16.f32 "
                 "{%0,%1,%2,%3}, {%4,%5,%6,%7}, {%8,%9}, {%0,%1,%2,%3};"
                 : "+f"(d[0]), "+f"(d[1]), "+f"(d[2]), "+f"(d[3])
                 : "r"(a[0]), "r"(a[1]), "r"(a[2]), "r"(a[3]), "r"(b[0]), "r"(b[1]));
}

// ---------------------------------------------------------------------------
// Kernel 1: tiny hypernet trunk
// ---------------------------------------------------------------------------
__global__ void hyper_trunk_kernel(const float* __restrict__ z,
                                   const float* __restrict__ Wa,
                                   const float* __restrict__ Wb) {
    __shared__ float h1[S_SAMPLES * 10];
    int tid = threadIdx.x;
    if (tid < S_SAMPLES * 10) {
        int s = tid / 10, w = tid % 10;
        float acc = 0.0f;
        #pragma unroll
        for (int c = 0; c < 8; c++) acc += z[s*8 + c] * Wa[w*8 + c];
        h1[tid] = elu1(acc);
    }
    __syncthreads();
    if (tid < S_SAMPLES * 10) {
        int s = tid / 10, v = tid % 10;
        float acc = 0.0f;
        #pragma unroll
        for (int w = 0; w < 10; w++) acc += h1[s*10 + w] * Wb[v*10 + w];
        g_hm[s*10 + v] = elu1(acc);
    }
}

// ---------------------------------------------------------------------------
// Kernel 2: x -> bf16 hi/lo split
// ---------------------------------------------------------------------------
__global__ void xconv_kernel(const float* __restrict__ x) {
    int i4 = blockIdx.x * blockDim.x + threadIdx.x;
    if (i4 * 4 >= BATCH * IN_DIM) return;
    float4 v = reinterpret_cast<const float4*>(x)[i4];
    float f[4] = {v.x, v.y, v.z, v.w};
    __nv_bfloat16 h[4], l[4];
    #pragma unroll
    for (int j = 0; j < 4; j++) {
        h[j] = __float2bfloat16(f[j]);
        l[j] = __float2bfloat16(f[j] - __bfloat162float(h[j]));
    }
    __nv_bfloat162 h01 = __halves2bfloat162(h[0], h[1]);
    __nv_bfloat162 h23 = __halves2bfloat162(h[2], h[3]);
    __nv_bfloat162 l01 = __halves2bfloat162(l[0], l[1]);
    __nv_bfloat162 l23 = __halves2bfloat162(l[2], l[3]);
    reinterpret_cast<uint2*>(g_xh)[i4] = make_uint2(*(uint32_t*)&h01, *(uint32_t*)&h23);
    reinterpret_cast<uint2*>(g_xl)[i4] = make_uint2(*(uint32_t*)&l01, *(uint32_t*)&l23);
}

// ---------------------------------------------------------------------------
// Kernel 3: theta[s][p] = sum_v hm[s][v] * Wc[p][v] -> bf16 hi/lo
// ---------------------------------------------------------------------------
__global__ void theta_kernel(const float* __restrict__ Wc) {
    __shared__ float hm_s[S_SAMPLES * 10];
    if (threadIdx.x < S_SAMPLES * 10) hm_s[threadIdx.x] = g_hm[threadIdx.x];
    __syncthreads();

    int p0 = (blockIdx.x * blockDim.x + threadIdx.x) * 2;
    if (p0 >= NPARAMS) return;

    float wc0[10], wc1[10];
    #pragma unroll
    for (int v = 0; v < 10; v++) {
        wc0[v] = Wc[(size_t)p0 * 10 + v];
        wc1[v] = Wc[(size_t)(p0 + 1) * 10 + v];
    }
    #pragma unroll
    for (int s = 0; s < S_SAMPLES; s++) {
        float a0 = 0.0f, a1 = 0.0f;
        #pragma unroll
        for (int v = 0; v < 10; v++) {
            a0 += hm_s[s*10 + v] * wc0[v];
            a1 += hm_s[s*10 + v] * wc1[v];
        }
        __nv_bfloat16 h0 = __float2bfloat16(a0), h1 = __float2bfloat16(a1);
        __nv_bfloat16 l0 = __float2bfloat16(a0 - __bfloat162float(h0));
        __nv_bfloat16 l1 = __float2bfloat16(a1 - __bfloat162float(h1));
        __nv_bfloat162 hp = __halves2bfloat162(h0, h1);
        __nv_bfloat162 lp = __halves2bfloat162(l0, l1);
        *reinterpret_cast<uint32_t*>(g_th + (size_t)s * NPARAMS + p0) = *(uint32_t*)&hp;
        *reinterpret_cast<uint32_t*>(g_tl + (size_t)s * NPARAMS + p0) = *(uint32_t*)&lp;
    }
}

// ---------------------------------------------------------------------------
// Kernel 4: mma.sync NT GEMM with bf16-split (3 HMMA per product term).
// C[m][n] = sum_k A[m][k]*B[n][k]. 128x128 CTA tile, 8 warps (4Mx2N),
// warp tile 32x64, KC=32, 2-stage cp.async pipeline.
// SMEM rows padded to 40 bf16 (80B) -> ldmatrix conflict-free.
// __launch_bounds__(256,2): cap regs at 128 so 2 CTAs/SM fit (160KB smem/SM).
// B fragments loaded per-j4 inside the MMA loop to keep live regs low.
// ---------------------------------------------------------------------------
#define KC      32
#define SMS     40                   // padded row stride (elems)
#define TILE_E  (128 * SMS)          // 5120 elems per tile
#define STAGE_E (4 * TILE_E)         // Ah, Al, Bh, Bl
#define SMEM_BYTES (2 * STAGE_E * 2) // 81920

template<bool LAYER1>
__global__ __launch_bounds__(256, 2)
void mma_gemm_kernel(const __nv_bfloat16* __restrict__ Ah_, const __nv_bfloat16* __restrict__ Al_,
                     unsigned long long sA, int lda,
                     const __nv_bfloat16* __restrict__ Bh_, const __nv_bfloat16* __restrict__ Bl_,
                     unsigned long long sB, int ldb,
                     float* __restrict__ Cf,
                     __nv_bfloat16* __restrict__ Ch, __nv_bfloat16* __restrict__ Cl,
                     unsigned long long sC, int ldc, int K) {
    extern __shared__ __nv_bfloat16 sm[];
    const int tid  = threadIdx.x;
    const int lane = tid & 31, wid = tid >> 5;
    const int warpM = wid & 3, warpN = wid >> 2;
    const int s  = blockIdx.z;
    const int m0 = blockIdx.y * 128;
    const int n0 = blockIdx.x * 128;

    const __nv_bfloat16* Ah = Ah_ + (size_t)s * sA;
    const __nv_bfloat16* Al = Al_ + (size_t)s * sA;
    const __nv_bfloat16* Bh = Bh_ + (size_t)s * sB;
    const __nv_bfloat16* Bl = Bl_ + (size_t)s * sB;

    float acc[2][8][4];
    #pragma unroll
    for (int i = 0; i < 2; i++)
        #pragma unroll
        for (int j = 0; j < 8; j++)
            #pragma unroll
            for (int q = 0; q < 4; q++) acc[i][j][q] = 0.0f;

    const int NC = K >> 5;

    // prefetch chunk 0
    {
        __nv_bfloat16* st = sm;
        #pragma unroll
        for (int it = 0; it < 2; it++) {
            int idx = it * 256 + tid;
            int r = idx >> 2, v = (idx & 3) * 8;
            cp_async16(&st[0 * TILE_E + r * SMS + v], Ah + (size_t)(m0 + r) * lda + v);
            cp_async16(&st[1 * TILE_E + r * SMS + v], Al + (size_t)(m0 + r) * lda + v);
            cp_async16(&st[2 * TILE_E + r * SMS + v], Bh + (size_t)(n0 + r) * ldb + v);
            cp_async16(&st[3 * TILE_E + r * SMS + v], Bl + (size_t)(n0 + r) * ldb + v);
        }
        cp_commit();
    }

    for (int c = 0; c < NC; c++) {
        if (c + 1 < NC) {
            __nv_bfloat16* st = sm + ((c + 1) & 1) * STAGE_E;
            const int k0 = (c + 1) * KC;
            #pragma unroll
            for (int it = 0; it < 2; it++) {
                int idx = it * 256 + tid;
                int r = idx >> 2, v = (idx & 3) * 8;
                cp_async16(&st[0 * TILE_E + r * SMS + v], Ah + (size_t)(m0 + r) * lda + k0 + v);
                cp_async16(&st[1 * TILE_E + r * SMS + v], Al + (size_t)(m0 + r) * lda + k0 + v);
                cp_async16(&st[2 * TILE_E + r * SMS + v], Bh + (size_t)(n0 + r) * ldb + k0 + v);
                cp_async16(&st[3 * TILE_E + r * SMS + v], Bl + (size_t)(n0 + r) * ldb + k0 + v);
            }
            cp_commit();
            cp_wait1();
        } else {
            cp_wait0();
        }
        __syncthreads();

        const uint32_t base = smem_u32(sm + (c & 1) * STAGE_E);
        #pragma unroll
        for (int ks = 0; ks < 2; ks++) {
            // A fragments (hi and lo) for this k16 step
            uint32_t afh[2][4], afl[2][4];
            #pragma unroll
            for (int i = 0; i < 2; i++) {
                uint32_t off = ((warpM * 32 + i * 16 + (lane & 15)) * SMS
                                + ks * 16 + ((lane >> 4) << 3)) * 2;
                ldsm4(afh[i], base + off);
                ldsm4(afl[i], base + TILE_E * 2 + off);
            }
            // B fragments loaded per-j4 (keeps live registers low)
            const int rr = (lane & 7) + ((lane >> 4) & 1) * 8;
            const int kh = (lane >> 3) & 1;
            #pragma unroll
            for (int j4 = 0; j4 < 4; j4++) {
                uint32_t off = ((warpN * 64 + j4 * 16 + rr) * SMS + ks * 16 + kh * 8) * 2;
                uint32_t bh4[4], bl4[4];
                ldsm4(bh4, base + 2 * TILE_E * 2 + off);
                ldsm4(bl4, base + 3 * TILE_E * 2 + off);
                #pragma unroll
                for (int i = 0; i < 2; i++) {
                    mma16816(acc[i][2*j4],   afh[i], &bh4[0]);
                    mma16816(acc[i][2*j4],   afh[i], &bl4[0]);
                    mma16816(acc[i][2*j4],   afl[i], &bh4[0]);
                    mma16816(acc[i][2*j4+1], afh[i], &bh4[2]);
                    mma16816(acc[i][2*j4+1], afh[i], &bl4[2]);
                    mma16816(acc[i][2*j4+1], afl[i], &bh4[2]);
                }
            }
        }
        __syncthreads();
    }

    // Epilogue. d-reg mapping: d0=(r, c), d1=(r, c+1), d2=(r+8, c), d3=(r+8, c+1)
    // with r = lane>>2, c = (lane&3)*2.
    #pragma unroll
    for (int i = 0; i < 2; i++) {
        int gm = m0 + warpM * 32 + i * 16 + (lane >> 2);
        #pragma unroll
        for (int j = 0; j < 8; j++) {
            int gn = n0 + warpN * 64 + j * 8 + (lane & 3) * 2;
            float* d = acc[i][j];
            if (LAYER1) {
                #pragma unroll
                for (int half = 0; half < 2; half++) {
                    int r = gm + half * 8;
                    float v0 = elu1(d[half * 2 + 0]);
                    float v1 = elu1(d[half * 2 + 1]);
                    __nv_bfloat16 h0 = __float2bfloat16(v0), h1 = __float2bfloat16(v1);
                    __nv_bfloat16 l0 = __float2bfloat16(v0 - __bfloat162float(h0));
                    __nv_bfloat16 l1 = __float2bfloat16(v1 - __bfloat162float(h1));
                    __nv_bfloat162 hp = __halves2bfloat162(h0, h1);
                    __nv_bfloat162 lp = __halves2bfloat162(l0, l1);
                    size_t off = (size_t)s * sC + (size_t)r * ldc + gn;
                    *reinterpret_cast<uint32_t*>(Ch + off) = *(uint32_t*)&hp;
                    *reinterpret_cast<uint32_t*>(Cl + off) = *(uint32_t*)&lp;
                }
            } else {
                size_t off0 = (size_t)s * sC + (size_t)gm * ldc + gn;
                size_t off1 = (size_t)s * sC + (size_t)(gm + 8) * ldc + gn;
                *reinterpret_cast<float2*>(Cf + off0) = make_float2(d[0], d[1]);
                *reinterpret_cast<float2*>(Cf + off1) = make_float2(d[2], d[3]);
            }
        }
    }
}

// ---------------------------------------------------------------------------
// Launch
// Inputs: x [1024,512], z [10,8], Wa [10,8], Wb [10,10], Wc [1048576,10], samples
// Output: y [10, 1024, 512] fp32
// ---------------------------------------------------------------------------
extern "C" void kernel_launch(void* const* d_in, const int* in_sizes, int n_in,
                              void* d_out, int out_size) {
    const float* x  = (const float*)d_in[0];
    const float* z  = (const float*)d_in[1];
    const float* Wa = (const float*)d_in[2];
    const float* Wb = (const float*)d_in[3];
    const float* Wc = (const float*)d_in[4];
    float* out = (float*)d_out;
    (void)in_sizes; (void)n_in; (void)out_size;

    __nv_bfloat16 *xh, *xl, *th, *tl, *ah, *al;
    cudaGetSymbolAddress((void**)&xh, g_xh);
    cudaGetSymbolAddress((void**)&xl, g_xl);
    cudaGetSymbolAddress((void**)&th, g_th);
    cudaGetSymbolAddress((void**)&tl, g_tl);
    cudaGetSymbolAddress((void**)&ah, g_ah);
    cudaGetSymbolAddress((void**)&al, g_al);

    static bool attr_done = false;
    if (!attr_done) {
        cudaFuncSetAttribute(mma_gemm_kernel<true>,
                             cudaFuncAttributeMaxDynamicSharedMemorySize, SMEM_BYTES);
        cudaFuncSetAttribute(mma_gemm_kernel<false>,
                             cudaFuncAttributeMaxDynamicSharedMemorySize, SMEM_BYTES);
        attr_done = true;
    }

    // 1) trunk + x conversion (independent)
    hyper_trunk_kernel<<<1, 128>>>(z, Wa, Wb);
    xconv_kernel<<<(BATCH * IN_DIM / 4 + 255) / 256, 256>>>(x);

    // 2) theta -> bf16 hi/lo
    theta_kernel<<<(NPARAMS / 2 + 255) / 256, 256>>>(Wc);

    // 3) a[s] = elu(x @ W1[s]^T)  M=1024, N=1024, K=512
    {
        dim3 grid(HID_DIM / 128, BATCH / 128, S_SAMPLES);
        mma_gemm_kernel<true><<<grid, 256, SMEM_BYTES>>>(
            xh, xl, 0ull, IN_DIM,
            th, tl, (unsigned long long)NPARAMS, IN_DIM,
            nullptr, ah, al,
            (unsigned long long)(BATCH * HID_DIM), HID_DIM, IN_DIM);
    }

    // 4) y[s] = a[s] @ W2[s]^T    M=1024, N=512, K=1024
    {
        dim3 grid(OUT_DIM / 128, BATCH / 128, S_SAMPLES);
        mma_gemm_kernel<false><<<grid, 256, SMEM_BYTES>>>(
            ah, al, (unsigned long long)(BATCH * HID_DIM), HID_DIM,
            th + N1, tl + N1, (unsigned long long)NPARAMS, HID_DIM,
            out, nullptr, nullptr,
            (unsigned long long)(BATCH * OUT_DIM), OUT_DIM, HID_DIM);
    }
}